// round 13
// baseline (speedup 1.0000x reference)
#include <cuda_runtime.h>
#include <cuda_fp16.h>
#include <math.h>
#include <stdint.h>

// Problem constants
#define BB 16
#define NN 243
#define JJ 17
#define CC 512
#define HH 8
#define MROWS (BB * NN * JJ)      // 66096
#define BNF   (BB * NN)           // 3888
#define KDIM  512

// Scratch (device globals: allocation-free per harness rules)
__device__ __half g_qkvh[(size_t)MROWS * 1536];
__device__ float g_y[(size_t)MROWS * CC];
__device__ __half g_xh[(size_t)MROWS * CC];
__device__ __half g_ah[(size_t)MROWS * CC];
__device__ __half g_w1h[1536 * 512];   // Wqkv^T fp16, [N][K]
__device__ __half g_w2h[512 * 512];    // Wproj^T fp16

// ---------------------------------------------------------------------------
// PTX helpers
// ---------------------------------------------------------------------------
__device__ __forceinline__ uint32_t smem_u32(const void* p) {
    uint32_t a;
    asm("{ .reg .u64 t; cvta.to.shared.u64 t, %1; cvt.u32.u64 %0, t; }"
        : "=r"(a) : "l"(p));
    return a;
}

#define CP_ASYNC16(dst, src, sz) \
    asm volatile("cp.async.cg.shared.global [%0], [%1], 16, %2;\n" \
                 :: "r"((uint32_t)(dst)), "l"(src), "r"(sz))
#define CP_COMMIT() asm volatile("cp.async.commit_group;\n" ::: "memory")
#define CP_WAIT1()  asm volatile("cp.async.wait_group 1;\n" ::: "memory")

#define LDSM4(r0, r1, r2, r3, a) \
    asm volatile("ldmatrix.sync.aligned.m8n8.x4.shared.b16 {%0,%1,%2,%3}, [%4];" \
                 : "=r"(r0), "=r"(r1), "=r"(r2), "=r"(r3) : "r"(a))

__device__ __forceinline__ void mma16816(float* c, const uint32_t* a, const uint32_t* b) {
    asm volatile(
        "mma.sync.aligned.m16n8k16.row.col.f32.f16.f16.f32 "
        "{%0,%1,%2,%3}, {%4,%5,%6,%7}, {%8,%9}, {%0,%1,%2,%3};\n"
        : "+f"(c[0]), "+f"(c[1]), "+f"(c[2]), "+f"(c[3])
        : "r"(a[0]), "r"(a[1]), "r"(a[2]), "r"(a[3]), "r"(b[0]), "r"(b[1]));
}

// ---------------------------------------------------------------------------
// fp16 HMMA GEMM: C(MxN) = A(MxK) @ B^T(NxK) + bias, fp32 accumulate.
// Output: fp16 (Ch) if Ch != null, else fp32 (Cf) with optional resid.
// BM=128, BN=128, BK=32, 256 threads (8 warps 2x4), warp tile 64x32.
// 2 CTAs/SM; 3-stage cp.async pipeline; ldmatrix from 80B-padded rows.
// ---------------------------------------------------------------------------
#define ROWB 80                        // padded row stride in bytes (40 fp16)
#define ST_A 0
#define ST_B (128 * ROWB)              // 10240
#define STAGE_BYTES (ST_B + 128 * ROWB)    // 20480
#define NSTAGE 3
#define GEMM_SMEM (NSTAGE * STAGE_BYTES)   // 61440

__device__ __forceinline__ void load_tile(
    uint32_t stage,
    const __half* __restrict__ Ah, const __half* __restrict__ Bh,
    int bm, int bn, int M, int kt, int tid)
{
    const int k0 = kt * 32;
#pragma unroll
    for (int i = 0; i < 2; i++) {     // A: 128 rows x 4 16B-chunks
        int q = i * 256 + tid;
        int row = q >> 2, c = q & 3;
        uint32_t dof = row * ROWB + c * 16;
        size_t ga = (size_t)(bm + row) * KDIM + k0 + c * 8;
        int p = ((bm + row) < M) ? 16 : 0;
        CP_ASYNC16(stage + ST_A + dof, Ah + ga, p);
    }
#pragma unroll
    for (int i = 0; i < 2; i++) {     // B: 128 rows x 4 16B-chunks
        int q = i * 256 + tid;
        int row = q >> 2, c = q & 3;
        uint32_t dof = row * ROWB + c * 16;
        size_t gb = (size_t)(bn + row) * KDIM + k0 + c * 8;
        CP_ASYNC16(stage + ST_B + dof, Bh + gb, 16);
    }
}

__global__ void __launch_bounds__(256, 2) gemm_mma(
    const __half* __restrict__ Ah, const __half* __restrict__ Bh,
    const float* __restrict__ bias, const float* __restrict__ resid,
    float* __restrict__ Cf, __half* __restrict__ Ch, int M, int N)
{
    extern __shared__ char smem[];
    const uint32_t sb = smem_u32(smem);
    const int tid = threadIdx.x;
    const int w = tid >> 5, lane = tid & 31;
    const int wm = w & 1;                 // 2 warp-rows of 64
    const int wn = w >> 1;                // 4 warp-cols of 32
    const int bn = blockIdx.x << 7;       // BN=128
    const int bm = blockIdx.y << 7;       // BM=128

    float acc[4][4][4];
#pragma unroll
    for (int i = 0; i < 4; i++)
#pragma unroll
        for (int j = 0; j < 4; j++)
#pragma unroll
            for (int e = 0; e < 4; e++) acc[i][j][e] = 0.f;

    const int lrow = lane & 15;
    const int lkb = (lane >> 4) << 4;     // k8-half byte offset
    const uint32_t a_lane_off = (wm * 64 + lrow) * ROWB + lkb;
    const uint32_t b_lane_off = (wn * 32 + lrow) * ROWB + lkb;

    const int T = KDIM / 32;              // 16
    load_tile(sb, Ah, Bh, bm, bn, M, 0, tid);
    CP_COMMIT();
    load_tile(sb + STAGE_BYTES, Ah, Bh, bm, bn, M, 1, tid);
    CP_COMMIT();

    int sidx = 0;
    for (int kt = 0; kt < T; kt++) {
        CP_WAIT1();                        // stage kt resident
        __syncthreads();

        if (kt + 2 < T)
            load_tile(sb + ((sidx + 2 >= NSTAGE) ? sidx + 2 - NSTAGE : sidx + 2) * STAGE_BYTES,
                      Ah, Bh, bm, bn, M, kt + 2, tid);
        CP_COMMIT();

        const uint32_t stage = sb + sidx * STAGE_BYTES;
#pragma unroll
        for (int kc = 0; kc < 2; kc++) {
            const uint32_t kbo = kc * 32;  // 16 fp16 = 32B per k16-chunk
            uint32_t ah[4][4], bh[4][2];
#pragma unroll
            for (int mi = 0; mi < 4; mi++) {
                uint32_t ad = stage + a_lane_off + mi * (16 * ROWB) + kbo;
                LDSM4(ah[mi][0], ah[mi][1], ah[mi][2], ah[mi][3], ad + ST_A);
            }
#pragma unroll
            for (int nj = 0; nj < 2; nj++) {      // 2 n16 tiles
                uint32_t bd = stage + b_lane_off + nj * (16 * ROWB) + kbo;
                uint32_t h0, h1, h2r, h3;
                LDSM4(h0, h1, h2r, h3, bd + ST_B);
                bh[nj * 2 + 0][0] = h0; bh[nj * 2 + 0][1] = h2r;
                bh[nj * 2 + 1][0] = h1; bh[nj * 2 + 1][1] = h3;
            }
#pragma unroll
            for (int mi = 0; mi < 4; mi++)
#pragma unroll
                for (int nq = 0; nq < 4; nq++)
                    mma16816(acc[mi][nq], ah[mi], bh[nq]);
        }
        sidx = (sidx + 1 >= NSTAGE) ? 0 : sidx + 1;
    }

    // Epilogue: thread g*4+t holds (m=g, n=2t) and (m=g+8, n=2t) per 16x8 tile
    const int g = lane >> 2, t = lane & 3;
#pragma unroll
    for (int mi = 0; mi < 4; mi++) {
#pragma unroll
        for (int ni = 0; ni < 4; ni++) {
            int col = bn + wn * 32 + ni * 8 + t * 2;
            float bb0 = bias[col], bb1 = bias[col + 1];
            int r0 = bm + wm * 64 + mi * 16 + g;
            int r1 = r0 + 8;
            if (Ch) {                     // fp16 output
                if (r0 < M)
                    *(__half2*)(Ch + (size_t)r0 * N + col) =
                        __halves2half2(__float2half(acc[mi][ni][0] + bb0),
                                       __float2half(acc[mi][ni][1] + bb1));
                if (r1 < M)
                    *(__half2*)(Ch + (size_t)r1 * N + col) =
                        __halves2half2(__float2half(acc[mi][ni][2] + bb0),
                                       __float2half(acc[mi][ni][3] + bb1));
            } else {                      // fp32 output (+resid)
                if (r0 < M) {
                    float2 o;
                    o.x = acc[mi][ni][0] + bb0;
                    o.y = acc[mi][ni][1] + bb1;
                    if (resid) {
                        const float2 rr = *(const float2*)(resid + (size_t)r0 * N + col);
                        o.x += rr.x; o.y += rr.y;
                    }
                    *(float2*)(Cf + (size_t)r0 * N + col) = o;
                }
                if (r1 < M) {
                    float2 o;
                    o.x = acc[mi][ni][2] + bb0;
                    o.y = acc[mi][ni][3] + bb1;
                    if (resid) {
                        const float2 rr = *(const float2*)(resid + (size_t)r1 * N + col);
                        o.x += rr.x; o.y += rr.y;
                    }
                    *(float2*)(Cf + (size_t)r1 * N + col) = o;
                }
            }
        }
    }
}

// ---------------------------------------------------------------------------
// Elementwise fp32 -> fp16 convert
// ---------------------------------------------------------------------------
__global__ void cvt_kernel(const float* __restrict__ src,
                           __half* __restrict__ dst, int n4) {
    int i = blockIdx.x * blockDim.x + threadIdx.x;
    if (i >= n4) return;
    float4 v = ((const float4*)src)[i];
    __half2* dp = (__half2*)dst;
    dp[2 * i]     = __halves2half2(__float2half(v.x), __float2half(v.y));
    dp[2 * i + 1] = __halves2half2(__float2half(v.z), __float2half(v.w));
}

// Transpose to fp16: W (KxN row-major) -> hiT (NxK row-major)
__global__ void wsplit_kernel(const float* __restrict__ W,
                              __half* __restrict__ hiT, int K, int N) {
    __shared__ float t[32][33];
    const int n0 = blockIdx.x * 32, k0 = blockIdx.y * 32;
    const int tx = threadIdx.x, ty = threadIdx.y;
    for (int r = ty; r < 32; r += 8)
        t[r][tx] = W[(size_t)(k0 + r) * N + n0 + tx];
    __syncthreads();
    for (int r = ty; r < 32; r += 8) {
        float v = t[tx][r];                       // (k0+tx, n0+r)
        hiT[(size_t)(n0 + r) * K + k0 + tx] = __float2half(v);
    }
}

// ---------------------------------------------------------------------------
// Attention: 2 heads per 128-thread block; qkv fp16 in, fp32 math, fp16 out.
// Vectorized uint4 loads (8 halves each); 3x3 register-tiled scores;
// register softmax; in-register triplet chain; register P@V.
// ---------------------------------------------------------------------------
#define APAD 68
__global__ __launch_bounds__(128)
void attn_kernel(const __half* __restrict__ qkv, __half* __restrict__ oh) {
    const int blk = blockIdx.x;           // 0 .. BNF*4-1
    const int bn = blk >> 2;
    const int h  = ((blk & 3) << 1) + (threadIdx.x >> 6);
    const int sl = threadIdx.x >> 6;      // slice 0/1
    const int d  = threadIdx.x & 63;

    __shared__ float qs[2][18][APAD];
    __shared__ float ks[2][18][APAD];
    __shared__ float vs[2][17][APAD];
    __shared__ float S[2][17][20];        // 80B rows (float4-aligned)

    // ---- vectorized load: 17 rows x 3 arrays x 8 uint4-chunks = 408 ----
    const __half* base = qkv + (size_t)bn * 17 * 1536 + h * 64;
    for (int idx = d; idx < 408; idx += 64) {
        int row = idx / 24;
        int rem = idx - row * 24;
        int arr = rem >> 3;
        int c = rem & 7;
        const uint4 raw = *(const uint4*)(base + (size_t)row * 1536 + arr * 512 + c * 8);
        const __half2* hp = (const __half2*)&raw;
        float4 lo, hi;
        float2 f;
        f = __half22float2(hp[0]); lo.x = f.x; lo.y = f.y;
        f = __half22float2(hp[1]); lo.z = f.x; lo.w = f.y;
        f = __half22float2(hp[2]); hi.x = f.x; hi.y = f.y;
        f = __half22float2(hp[3]); hi.z = f.x; hi.w = f.y;
        float* dst = (arr == 0) ? &qs[sl][row][0]
                   : (arr == 1) ? &ks[sl][row][0] : &vs[sl][row][0];
        *(float4*)(dst + c * 8) = lo;
        *(float4*)(dst + c * 8 + 4) = hi;
    }
    qs[sl][17][d] = 0.f;                  // zero pad row
    ks[sl][17][d] = 0.f;
    __syncthreads();

    // ---- scores: 6x6 grid of 3x3 register tiles; threads 0..35 ----
    if (d < 36) {
        const int i0 = (d / 6) * 3;
        const int j0 = (d % 6) * 3;
        float a[3][3];
#pragma unroll
        for (int r = 0; r < 3; r++)
#pragma unroll
            for (int s = 0; s < 3; s++) a[r][s] = 0.f;

#pragma unroll
        for (int c = 0; c < 8; c++) {     // 8 chunks of 8 along head dim
            float qv[3][8], kv[3][8];
#pragma unroll
            for (int r = 0; r < 3; r++) {
                *(float4*)&qv[r][0] = *(const float4*)&qs[sl][i0 + r][c * 8];
                *(float4*)&qv[r][4] = *(const float4*)&qs[sl][i0 + r][c * 8 + 4];
                *(float4*)&kv[r][0] = *(const float4*)&ks[sl][j0 + r][c * 8];
                *(float4*)&kv[r][4] = *(const float4*)&ks[sl][j0 + r][c * 8 + 4];
            }
#pragma unroll
            for (int r = 0; r < 3; r++)
#pragma unroll
                for (int s = 0; s < 3; s++)
#pragma unroll
                    for (int e = 0; e < 8; e++)
                        a[r][s] += qv[r][e] * kv[s][e];
        }
#pragma unroll
        for (int r = 0; r < 3; r++)
#pragma unroll
            for (int s = 0; s < 3; s++)
                if (i0 + r < 17 && j0 + s < 17)
                    S[sl][i0 + r][j0 + s] = a[r][s] * 0.125f;
    }
    __syncthreads();

    // ---- softmax: row in registers ----
    if (d < 17) {
        float r[17];
        *(float4*)&r[0]  = *(const float4*)&S[sl][d][0];
        *(float4*)&r[4]  = *(const float4*)&S[sl][d][4];
        *(float4*)&r[8]  = *(const float4*)&S[sl][d][8];
        *(float4*)&r[12] = *(const float4*)&S[sl][d][12];
        r[16] = S[sl][d][16];
        float mx = r[0];
#pragma unroll
        for (int j = 1; j < 17; j++) mx = fmaxf(mx, r[j]);
        float sum = 0.f;
#pragma unroll
        for (int j = 0; j < 17; j++) {
            r[j] = expf(r[j] - mx);
            sum += r[j];
        }
        float inv = 1.f / sum;
#pragma unroll
        for (int j = 0; j < 17; j++) r[j] *= inv;
        *(float4*)&S[sl][d][0]  = *(const float4*)&r[0];
        *(float4*)&S[sl][d][4]  = *(const float4*)&r[4];
        *(float4*)&S[sl][d][8]  = *(const float4*)&r[8];
        *(float4*)&S[sl][d][12] = *(const float4*)&r[12];
        S[sl][d][16] = r[16];
    }
    __syncthreads();

    // ---- skeleton triplets: in-register dependency chain (1 thread/slice) --
    if (d == 0) {
        float s10 = S[sl][1][0],  s12 = S[sl][1][2],  s21 = S[sl][2][1];
        float s23 = S[sl][2][3],  s32 = S[sl][3][2];
        float s40 = S[sl][4][0],  s45 = S[sl][4][5],  s54 = S[sl][5][4];
        float s56 = S[sl][5][6],  s65 = S[sl][6][5];
        float s70 = S[sl][7][0],  s78 = S[sl][7][8],  s87 = S[sl][8][7];
        float s89 = S[sl][8][9],  s98 = S[sl][9][8];
        float s9a = S[sl][9][10], sa9 = S[sl][10][9];
        float s8b = S[sl][8][11], sb8 = S[sl][11][8];
        float sbc = S[sl][11][12], scb = S[sl][12][11];
        float scd = S[sl][12][13], sdc = S[sl][13][12];
        float s8e = S[sl][8][14], se8 = S[sl][14][8];
        float sef = S[sl][14][15], sfe = S[sl][15][14];
        float sfg = S[sl][15][16], sgf = S[sl][16][15];
        float hh;
        hh = s10 * 0.5f; s12 += hh; s21 += hh;       // {0,1,2}
        hh = s21 * 0.5f; s23 += hh; s32 += hh;       // {1,2,3}
        hh = s40 * 0.5f; s45 += hh; s54 += hh;       // {0,4,5}
        hh = s54 * 0.5f; s56 += hh; s65 += hh;       // {4,5,6}
        hh = s70 * 0.5f; s78 += hh; s87 += hh;       // {0,7,8}
        hh = s87 * 0.5f; s89 += hh; s98 += hh;       // {7,8,9}
        hh = s98 * 0.5f; s9a += hh; sa9 += hh;       // {8,9,10}
        hh = s87 * 0.5f; s8b += hh; sb8 += hh;       // {7,8,11}
        hh = sb8 * 0.5f; sbc += hh; scb += hh;       // {8,11,12}
        hh = scb * 0.5f; scd += hh; sdc += hh;       // {11,12,13}
        hh = s87 * 0.5f; s8e += hh; se8 += hh;       // {7,8,14}
        hh = se8 * 0.5f; sef += hh; sfe += hh;       // {8,14,15}
        hh = sfe * 0.5f; sfg += hh; sgf += hh;       // {14,15,16}
        S[sl][1][2] = s12;   S[sl][2][1] = s21;
        S[sl][2][3] = s23;   S[sl][3][2] = s32;
        S[sl][4][5] = s45;   S[sl][5][4] = s54;
        S[sl][5][6] = s56;   S[sl][6][5] = s65;
        S[sl][7][8] = s78;   S[sl][8][7] = s87;
        S[sl][8][9] = s89;   S[sl][9][8] = s98;
        S[sl][9][10] = s9a;  S[sl][10][9] = sa9;
        S[sl][8][11] = s8b;  S[sl][11][8] = sb8;
        S[sl][11][12] = sbc; S[sl][12][11] = scb;
        S[sl][12][13] = scd; S[sl][13][12] = sdc;
        S[sl][8][14] = s8e;  S[sl][14][8] = se8;
        S[sl][14][15] = sef; S[sl][15][14] = sfe;
        S[sl][15][16] = sfg; S[sl][16][15] = sgf;
    }
    __syncthreads();

    // ---- P@V: v cached in registers; S rows via float4 broadcast ----
    float v[17];
#pragma unroll
    for (int j = 0; j < 17; j++) v[j] = vs[sl][j][d];
#pragma unroll
    for (int i = 0; i < 17; i++) {
        const float4 s0 = *(const float4*)&S[sl][i][0];
        const float4 s1 = *(const float4*)&S[sl][i][4];
        const float4 s2 = *(const float4*)&S[sl][i][8];
        const float4 s3 = *(const float4*)&S[sl][i][12];
        const float s16 = S[sl][i][16];
        float o = s0.x * v[0] + s0.y * v[1] + s0.z * v[2] + s0.w * v[3]
                + s1.x * v[4] + s1.y * v[5] + s1.z * v[6] + s1.w * v[7]
                + s2.x * v[8] + s2.y * v[9] + s2.z * v[10] + s2.w * v[11]
                + s3.x * v[12] + s3.y * v[13] + s3.z * v[14] + s3.w * v[15]
                + s16 * v[16];
        oh[((size_t)(bn * 17 + i)) * 512 + h * 64 + d] = __float2half(o);
    }
}

// ---------------------------------------------------------------------------
// LayerNorm (no affine) over last dim 512
// ---------------------------------------------------------------------------
__global__ __launch_bounds__(128)
void ln_kernel(const float* __restrict__ Y, float* __restrict__ O) {
    const int row = blockIdx.x;
    const int t = threadIdx.x;
    const float4* yp = reinterpret_cast<const float4*>(Y + (size_t)row * 512);
    float4* op = reinterpret_cast<float4*>(O + (size_t)row * 512);

    float4 v = yp[t];
    float s = v.x + v.y + v.z + v.w;
    float q = v.x * v.x + v.y * v.y + v.z * v.z + v.w * v.w;
#pragma unroll
    for (int o = 16; o > 0; o >>= 1) {
        s += __shfl_xor_sync(0xffffffffu, s, o);
        q += __shfl_xor_sync(0xffffffffu, q, o);
    }
    __shared__ float ss[4], sq[4];
    int w = t >> 5;
    if ((t & 31) == 0) { ss[w] = s; sq[w] = q; }
    __syncthreads();
    s = ss[0] + ss[1] + ss[2] + ss[3];
    q = sq[0] + sq[1] + sq[2] + sq[3];

    const float inv512 = 1.f / 512.f;
    float mean = s * inv512;
    float var = q * inv512 - mean * mean;
    float r = rsqrtf(var + 1e-5f);

    float4 o4;
    o4.x = (v.x - mean) * r;
    o4.y = (v.y - mean) * r;
    o4.z = (v.z - mean) * r;
    o4.w = (v.w - mean) * r;
    op[t] = o4;
}

// ---------------------------------------------------------------------------
extern "C" void kernel_launch(void* const* d_in, const int* in_sizes, int n_in,
                              void* d_out, int out_size) {
    const float* x     = (const float*)d_in[0];
    const float* Wqkv  = (const float*)d_in[1];
    const float* bqkv  = (const float*)d_in[2];
    const float* Wproj = (const float*)d_in[3];
    const float* bproj = (const float*)d_in[4];
    float* out = (float*)d_out;

    float *y;
    __half *qkvh, *xh, *ah, *w1h, *w2h;
    cudaGetSymbolAddress((void**)&qkvh, g_qkvh);
    cudaGetSymbolAddress((void**)&y, g_y);
    cudaGetSymbolAddress((void**)&xh, g_xh);
    cudaGetSymbolAddress((void**)&ah, g_ah);
    cudaGetSymbolAddress((void**)&w1h, g_w1h);
    cudaGetSymbolAddress((void**)&w2h, g_w2h);

    cudaFuncSetAttribute(gemm_mma, cudaFuncAttributeMaxDynamicSharedMemorySize, GEMM_SMEM);

    // 1) converts
    const int n4 = MROWS * CC / 4;
    cvt_kernel<<<(n4 + 255) / 256, 256>>>(x, xh, n4);
    wsplit_kernel<<<dim3(1536 / 32, 512 / 32), dim3(32, 8)>>>(Wqkv, w1h, 512, 1536);
    wsplit_kernel<<<dim3(512 / 32, 512 / 32), dim3(32, 8)>>>(Wproj, w2h, 512, 512);

    // 2) GEMM1: qkv = x @ Wqkv + bqkv (fp16 out)
    gemm_mma<<<dim3(1536 / 128, (MROWS + 127) / 128), 256, GEMM_SMEM>>>(
        xh, w1h, bqkv, nullptr, nullptr, qkvh, MROWS, 1536);

    // 3) attention (fp16 in/out)
    attn_kernel<<<BNF * 4, 128>>>(qkvh, ah);

    // 4) GEMM2: y = att @ Wproj + bproj + x (fp32 out + resid)
    gemm_mma<<<dim3(512 / 128, (MROWS + 127) / 128), 256, GEMM_SMEM>>>(
        ah, w2h, bproj, x, y, nullptr, MROWS, 512);

    // 5) LayerNorm
    ln_kernel<<<MROWS, 128>>>(y, out);
}

// round 14
// speedup vs baseline: 1.0973x; 1.0973x over previous
#include <cuda_runtime.h>
#include <cuda_fp16.h>
#include <math.h>
#include <stdint.h>

// Problem constants
#define BB 16
#define NN 243
#define JJ 17
#define CC 512
#define HH 8
#define MROWS (BB * NN * JJ)      // 66096
#define BNF   (BB * NN)           // 3888
#define KDIM  512

// Scratch (device globals: allocation-free per harness rules)
__device__ __half g_qkvh[(size_t)MROWS * 1536];
__device__ float g_y[(size_t)MROWS * CC];
__device__ __half g_xh[(size_t)MROWS * CC];
__device__ __half g_ah[(size_t)MROWS * CC];
__device__ __half g_w1h[1536 * 512];   // Wqkv^T fp16, [N][K]
__device__ __half g_w2h[512 * 512];    // Wproj^T fp16

// ---------------------------------------------------------------------------
// PTX helpers
// ---------------------------------------------------------------------------
__device__ __forceinline__ uint32_t smem_u32(const void* p) {
    uint32_t a;
    asm("{ .reg .u64 t; cvta.to.shared.u64 t, %1; cvt.u32.u64 %0, t; }"
        : "=r"(a) : "l"(p));
    return a;
}

#define CP_ASYNC16(dst, src, sz) \
    asm volatile("cp.async.cg.shared.global [%0], [%1], 16, %2;\n" \
                 :: "r"((uint32_t)(dst)), "l"(src), "r"(sz))
#define CP_COMMIT() asm volatile("cp.async.commit_group;\n" ::: "memory")
#define CP_WAIT0()  asm volatile("cp.async.wait_group 0;\n" ::: "memory")

#define LDSM4(r0, r1, r2, r3, a) \
    asm volatile("ldmatrix.sync.aligned.m8n8.x4.shared.b16 {%0,%1,%2,%3}, [%4];" \
                 : "=r"(r0), "=r"(r1), "=r"(r2), "=r"(r3) : "r"(a))

__device__ __forceinline__ void mma16816(float* c, const uint32_t* a, const uint32_t* b) {
    asm volatile(
        "mma.sync.aligned.m16n8k16.row.col.f32.f16.f16.f32 "
        "{%0,%1,%2,%3}, {%4,%5,%6,%7}, {%8,%9}, {%0,%1,%2,%3};\n"
        : "+f"(c[0]), "+f"(c[1]), "+f"(c[2]), "+f"(c[3])
        : "r"(a[0]), "r"(a[1]), "r"(a[2]), "r"(a[3]), "r"(b[0]), "r"(b[1]));
}

// ---------------------------------------------------------------------------
// fp16 HMMA GEMM: C(MxN) = A(MxK) @ B^T(NxK) + bias, fp32 accumulate.
// Output: fp16 (Ch) if Ch != null, else fp32 (Cf) with optional resid.
// BM=128, BN=128, BK=64, 256 threads (8 warps 2x4), warp tile 64x32.
// 2 CTAs/SM; 2-stage double buffer (8 syncs instead of 16);
// ldmatrix from 144B-padded rows (8 consecutive rows -> 8 distinct 16B banks).
// ---------------------------------------------------------------------------
#define ROWB 144                       // 128B of k-data + 16B pad
#define ST_A 0
#define ST_B (128 * ROWB)              // 18432
#define STAGE_BYTES (ST_B + 128 * ROWB)    // 36864
#define GEMM_SMEM (2 * STAGE_BYTES)        // 73728

__device__ __forceinline__ void load_tile(
    uint32_t stage,
    const __half* __restrict__ Ah, const __half* __restrict__ Bh,
    int bm, int bn, int M, int kt, int tid)
{
    const int k0 = kt * 64;
#pragma unroll
    for (int i = 0; i < 4; i++) {     // A: 128 rows x 8 16B-chunks
        int q = i * 256 + tid;
        int row = q >> 3, c = q & 7;
        uint32_t dof = row * ROWB + c * 16;
        size_t ga = (size_t)(bm + row) * KDIM + k0 + c * 8;
        int p = ((bm + row) < M) ? 16 : 0;
        CP_ASYNC16(stage + ST_A + dof, Ah + ga, p);
    }
#pragma unroll
    for (int i = 0; i < 4; i++) {     // B: 128 rows x 8 16B-chunks
        int q = i * 256 + tid;
        int row = q >> 3, c = q & 7;
        uint32_t dof = row * ROWB + c * 16;
        size_t gb = (size_t)(bn + row) * KDIM + k0 + c * 8;
        CP_ASYNC16(stage + ST_B + dof, Bh + gb, 16);
    }
}

__global__ void __launch_bounds__(256, 2) gemm_mma(
    const __half* __restrict__ Ah, const __half* __restrict__ Bh,
    const float* __restrict__ bias, const float* __restrict__ resid,
    float* __restrict__ Cf, __half* __restrict__ Ch, int M, int N)
{
    extern __shared__ char smem[];
    const uint32_t sb = smem_u32(smem);
    const int tid = threadIdx.x;
    const int w = tid >> 5, lane = tid & 31;
    const int wm = w & 1;                 // 2 warp-rows of 64
    const int wn = w >> 1;                // 4 warp-cols of 32
    const int bn = blockIdx.x << 7;       // BN=128
    const int bm = blockIdx.y << 7;       // BM=128

    float acc[4][4][4];
#pragma unroll
    for (int i = 0; i < 4; i++)
#pragma unroll
        for (int j = 0; j < 4; j++)
#pragma unroll
            for (int e = 0; e < 4; e++) acc[i][j][e] = 0.f;

    const int lrow = lane & 15;
    const int lkb = (lane >> 4) << 4;     // k8-half byte offset within k16 chunk
    const uint32_t a_lane_off = (wm * 64 + lrow) * ROWB + lkb;
    const uint32_t b_lane_off = (wn * 32 + lrow) * ROWB + lkb;

    const int T = KDIM / 64;              // 8
    load_tile(sb, Ah, Bh, bm, bn, M, 0, tid);
    CP_COMMIT();

    for (int kt = 0; kt < T; kt++) {
        CP_WAIT0();                        // tile kt resident (single group)
        __syncthreads();                   // all warps done with other buffer

        if (kt + 1 < T) {
            load_tile(sb + ((kt + 1) & 1) * STAGE_BYTES, Ah, Bh, bm, bn, M, kt + 1, tid);
            CP_COMMIT();
        }

        const uint32_t stage = sb + (kt & 1) * STAGE_BYTES;
#pragma unroll
        for (int kc = 0; kc < 4; kc++) {   // 4 k16-chunks per BK=64
            const uint32_t kbo = kc * 32;  // 16 fp16 = 32B per k16-chunk
            uint32_t ah[4][4], bh[4][2];
#pragma unroll
            for (int mi = 0; mi < 4; mi++) {
                uint32_t ad = stage + a_lane_off + mi * (16 * ROWB) + kbo;
                LDSM4(ah[mi][0], ah[mi][1], ah[mi][2], ah[mi][3], ad + ST_A);
            }
#pragma unroll
            for (int nj = 0; nj < 2; nj++) {      // 2 n16 tiles
                uint32_t bd = stage + b_lane_off + nj * (16 * ROWB) + kbo;
                uint32_t h0, h1, h2r, h3;
                LDSM4(h0, h1, h2r, h3, bd + ST_B);
                bh[nj * 2 + 0][0] = h0; bh[nj * 2 + 0][1] = h2r;
                bh[nj * 2 + 1][0] = h1; bh[nj * 2 + 1][1] = h3;
            }
#pragma unroll
            for (int mi = 0; mi < 4; mi++)
#pragma unroll
                for (int nq = 0; nq < 4; nq++)
                    mma16816(acc[mi][nq], ah[mi], bh[nq]);
        }
    }

    // Epilogue: thread g*4+t holds (m=g, n=2t) and (m=g+8, n=2t) per 16x8 tile
    const int g = lane >> 2, t = lane & 3;
#pragma unroll
    for (int mi = 0; mi < 4; mi++) {
#pragma unroll
        for (int ni = 0; ni < 4; ni++) {
            int col = bn + wn * 32 + ni * 8 + t * 2;
            float bb0 = bias[col], bb1 = bias[col + 1];
            int r0 = bm + wm * 64 + mi * 16 + g;
            int r1 = r0 + 8;
            if (Ch) {                     // fp16 output
                if (r0 < M)
                    *(__half2*)(Ch + (size_t)r0 * N + col) =
                        __halves2half2(__float2half(acc[mi][ni][0] + bb0),
                                       __float2half(acc[mi][ni][1] + bb1));
                if (r1 < M)
                    *(__half2*)(Ch + (size_t)r1 * N + col) =
                        __halves2half2(__float2half(acc[mi][ni][2] + bb0),
                                       __float2half(acc[mi][ni][3] + bb1));
            } else {                      // fp32 output (+resid)
                if (r0 < M) {
                    float2 o;
                    o.x = acc[mi][ni][0] + bb0;
                    o.y = acc[mi][ni][1] + bb1;
                    if (resid) {
                        const float2 rr = *(const float2*)(resid + (size_t)r0 * N + col);
                        o.x += rr.x; o.y += rr.y;
                    }
                    *(float2*)(Cf + (size_t)r0 * N + col) = o;
                }
                if (r1 < M) {
                    float2 o;
                    o.x = acc[mi][ni][2] + bb0;
                    o.y = acc[mi][ni][3] + bb1;
                    if (resid) {
                        const float2 rr = *(const float2*)(resid + (size_t)r1 * N + col);
                        o.x += rr.x; o.y += rr.y;
                    }
                    *(float2*)(Cf + (size_t)r1 * N + col) = o;
                }
            }
        }
    }
}

// ---------------------------------------------------------------------------
// Elementwise fp32 -> fp16 convert
// ---------------------------------------------------------------------------
__global__ void cvt_kernel(const float* __restrict__ src,
                           __half* __restrict__ dst, int n4) {
    int i = blockIdx.x * blockDim.x + threadIdx.x;
    if (i >= n4) return;
    float4 v = ((const float4*)src)[i];
    __half2* dp = (__half2*)dst;
    dp[2 * i]     = __halves2half2(__float2half(v.x), __float2half(v.y));
    dp[2 * i + 1] = __halves2half2(__float2half(v.z), __float2half(v.w));
}

// Transpose to fp16: W (KxN row-major) -> hiT (NxK row-major)
__global__ void wsplit_kernel(const float* __restrict__ W,
                              __half* __restrict__ hiT, int K, int N) {
    __shared__ float t[32][33];
    const int n0 = blockIdx.x * 32, k0 = blockIdx.y * 32;
    const int tx = threadIdx.x, ty = threadIdx.y;
    for (int r = ty; r < 32; r += 8)
        t[r][tx] = W[(size_t)(k0 + r) * N + n0 + tx];
    __syncthreads();
    for (int r = ty; r < 32; r += 8) {
        float v = t[tx][r];                       // (k0+tx, n0+r)
        hiT[(size_t)(n0 + r) * K + k0 + tx] = __float2half(v);
    }
}

// ---------------------------------------------------------------------------
// Attention (R12 proven version): 2 heads per 128-thread block; qkv fp16 in,
// fp32 math, fp16 out. 3x3 register-tiled scores; padded rows; register P@V.
// ---------------------------------------------------------------------------
#define APAD 68
__global__ __launch_bounds__(128)
void attn_kernel(const __half* __restrict__ qkv, __half* __restrict__ oh) {
    const int blk = blockIdx.x;           // 0 .. BNF*4-1
    const int bn = blk >> 2;
    const int h  = ((blk & 3) << 1) + (threadIdx.x >> 6);
    const int sl = threadIdx.x >> 6;      // slice 0/1
    const int d  = threadIdx.x & 63;

    __shared__ float qs[2][18][APAD];
    __shared__ float ks[2][18][APAD];
    __shared__ float vs[2][17][APAD];
    __shared__ float S[2][17][20];        // 80B rows (float4-aligned)

    const __half* base = qkv + (size_t)bn * 17 * 1536 + h * 64;
#pragma unroll
    for (int j = 0; j < 17; j++) {
        const __half* r = base + (size_t)j * 1536;
        qs[sl][j][d] = __half2float(r[d]);
        ks[sl][j][d] = __half2float(r[512 + d]);
        vs[sl][j][d] = __half2float(r[1024 + d]);
    }
    qs[sl][17][d] = 0.f;                  // zero pad row
    ks[sl][17][d] = 0.f;
    __syncthreads();

    // Scores: 6x6 grid of 3x3 tiles over the padded 18x18 domain; threads 0..35
    if (d < 36) {
        const int i0 = (d / 6) * 3;
        const int j0 = (d % 6) * 3;
        float a[3][3];
#pragma unroll
        for (int r = 0; r < 3; r++)
#pragma unroll
            for (int s = 0; s < 3; s++) a[r][s] = 0.f;

#pragma unroll
        for (int c = 0; c < 8; c++) {     // 8 chunks of 8 along head dim
            float qv[3][8], kv[3][8];
#pragma unroll
            for (int r = 0; r < 3; r++) {
                *(float4*)&qv[r][0] = *(const float4*)&qs[sl][i0 + r][c * 8];
                *(float4*)&qv[r][4] = *(const float4*)&qs[sl][i0 + r][c * 8 + 4];
                *(float4*)&kv[r][0] = *(const float4*)&ks[sl][j0 + r][c * 8];
                *(float4*)&kv[r][4] = *(const float4*)&ks[sl][j0 + r][c * 8 + 4];
            }
#pragma unroll
            for (int r = 0; r < 3; r++)
#pragma unroll
                for (int s = 0; s < 3; s++)
#pragma unroll
                    for (int e = 0; e < 8; e++)
                        a[r][s] += qv[r][e] * kv[s][e];
        }
#pragma unroll
        for (int r = 0; r < 3; r++)
#pragma unroll
            for (int s = 0; s < 3; s++)
                if (i0 + r < 17 && j0 + s < 17)
                    S[sl][i0 + r][j0 + s] = a[r][s] * 0.125f;
    }
    __syncthreads();

    if (d < 17) {
        float mx = -1e30f;
#pragma unroll
        for (int j = 0; j < 17; j++) mx = fmaxf(mx, S[sl][d][j]);
        float sum = 0.f;
#pragma unroll
        for (int j = 0; j < 17; j++) {
            float e = expf(S[sl][d][j] - mx);
            S[sl][d][j] = e;
            sum += e;
        }
        float inv = 1.f / sum;
#pragma unroll
        for (int j = 0; j < 17; j++) S[sl][d][j] *= inv;
    }
    __syncthreads();

    if (d == 0) {
        const int trip[13][3] = {
            {0,1,2},{1,2,3},{0,4,5},{4,5,6},{0,7,8},{7,8,9},{8,9,10},
            {7,8,11},{8,11,12},{11,12,13},{7,8,14},{8,14,15},{14,15,16}};
#pragma unroll
        for (int tt = 0; tt < 13; tt++) {
            int jp = trip[tt][0], j = trip[tt][1], jc = trip[tt][2];
            float half = S[sl][j][jp] * 0.5f;
            S[sl][j][jc] += half;
            S[sl][jc][j] += half;
        }
    }
    __syncthreads();

    // P@V: v cached in registers; S rows via float4 broadcast
    float v[17];
#pragma unroll
    for (int j = 0; j < 17; j++) v[j] = vs[sl][j][d];
#pragma unroll
    for (int i = 0; i < 17; i++) {
        const float4 s0 = *(const float4*)&S[sl][i][0];
        const float4 s1 = *(const float4*)&S[sl][i][4];
        const float4 s2 = *(const float4*)&S[sl][i][8];
        const float4 s3 = *(const float4*)&S[sl][i][12];
        const float s16 = S[sl][i][16];
        float o = s0.x * v[0] + s0.y * v[1] + s0.z * v[2] + s0.w * v[3]
                + s1.x * v[4] + s1.y * v[5] + s1.z * v[6] + s1.w * v[7]
                + s2.x * v[8] + s2.y * v[9] + s2.z * v[10] + s2.w * v[11]
                + s3.x * v[12] + s3.y * v[13] + s3.z * v[14] + s3.w * v[15]
                + s16 * v[16];
        oh[((size_t)(bn * 17 + i)) * 512 + h * 64 + d] = __float2half(o);
    }
}

// ---------------------------------------------------------------------------
// LayerNorm (no affine) over last dim 512
// ---------------------------------------------------------------------------
__global__ __launch_bounds__(128)
void ln_kernel(const float* __restrict__ Y, float* __restrict__ O) {
    const int row = blockIdx.x;
    const int t = threadIdx.x;
    const float4* yp = reinterpret_cast<const float4*>(Y + (size_t)row * 512);
    float4* op = reinterpret_cast<float4*>(O + (size_t)row * 512);

    float4 v = yp[t];
    float s = v.x + v.y + v.z + v.w;
    float q = v.x * v.x + v.y * v.y + v.z * v.z + v.w * v.w;
#pragma unroll
    for (int o = 16; o > 0; o >>= 1) {
        s += __shfl_xor_sync(0xffffffffu, s, o);
        q += __shfl_xor_sync(0xffffffffu, q, o);
    }
    __shared__ float ss[4], sq[4];
    int w = t >> 5;
    if ((t & 31) == 0) { ss[w] = s; sq[w] = q; }
    __syncthreads();
    s = ss[0] + ss[1] + ss[2] + ss[3];
    q = sq[0] + sq[1] + sq[2] + sq[3];

    const float inv512 = 1.f / 512.f;
    float mean = s * inv512;
    float var = q * inv512 - mean * mean;
    float r = rsqrtf(var + 1e-5f);

    float4 o4;
    o4.x = (v.x - mean) * r;
    o4.y = (v.y - mean) * r;
    o4.z = (v.z - mean) * r;
    o4.w = (v.w - mean) * r;
    op[t] = o4;
}

// ---------------------------------------------------------------------------
extern "C" void kernel_launch(void* const* d_in, const int* in_sizes, int n_in,
                              void* d_out, int out_size) {
    const float* x     = (const float*)d_in[0];
    const float* Wqkv  = (const float*)d_in[1];
    const float* bqkv  = (const float*)d_in[2];
    const float* Wproj = (const float*)d_in[3];
    const float* bproj = (const float*)d_in[4];
    float* out = (float*)d_out;

    float *y;
    __half *qkvh, *xh, *ah, *w1h, *w2h;
    cudaGetSymbolAddress((void**)&qkvh, g_qkvh);
    cudaGetSymbolAddress((void**)&y, g_y);
    cudaGetSymbolAddress((void**)&xh, g_xh);
    cudaGetSymbolAddress((void**)&ah, g_ah);
    cudaGetSymbolAddress((void**)&w1h, g_w1h);
    cudaGetSymbolAddress((void**)&w2h, g_w2h);

    cudaFuncSetAttribute(gemm_mma, cudaFuncAttributeMaxDynamicSharedMemorySize, GEMM_SMEM);

    // 1) converts
    const int n4 = MROWS * CC / 4;
    cvt_kernel<<<(n4 + 255) / 256, 256>>>(x, xh, n4);
    wsplit_kernel<<<dim3(1536 / 32, 512 / 32), dim3(32, 8)>>>(Wqkv, w1h, 512, 1536);
    wsplit_kernel<<<dim3(512 / 32, 512 / 32), dim3(32, 8)>>>(Wproj, w2h, 512, 512);

    // 2) GEMM1: qkv = x @ Wqkv + bqkv (fp16 out)
    gemm_mma<<<dim3(1536 / 128, (MROWS + 127) / 128), 256, GEMM_SMEM>>>(
        xh, w1h, bqkv, nullptr, nullptr, qkvh, MROWS, 1536);

    // 3) attention (fp16 in/out)
    attn_kernel<<<BNF * 4, 128>>>(qkvh, ah);

    // 4) GEMM2: y = att @ Wproj + bproj + x (fp32 out + resid)
    gemm_mma<<<dim3(512 / 128, (MROWS + 127) / 128), 256, GEMM_SMEM>>>(
        ah, w2h, bproj, x, y, nullptr, MROWS, 512);

    // 5) LayerNorm
    ln_kernel<<<MROWS, 128>>>(y, out);
}